// round 1
// baseline (speedup 1.0000x reference)
#include <cuda_runtime.h>

#define N_ROWS 1024   // N (decoder rows)
#define P_PIX  1024   // P (pixels)
#define E_DIM  512    // ENC / TAG / LANG (all 512)
#define A_DIM  256    // ATT

// Scratch (device globals — no allocation allowed)
__device__ float g_att1[P_PIX * A_DIM];   // (P, A)
__device__ float g_att2[N_ROWS * A_DIM];  // (N, A)
__device__ float g_att3[N_ROWS * A_DIM];  // (N, A)
__device__ float g_att [N_ROWS * P_PIX];  // (N, P) pre-softmax scores

// ---------------------------------------------------------------------------
// Kernel 1: three uniform GEMMs C = A * B^T + bias  (M=1024, N=256, K=512)
// z=0: att1 = enc @ We^T + be
// z=1: att2 = dh  @ Wt^T + bt
// z=2: att3 = lo  @ Wl^T + bl
// BM=32, BN=64, BK=16, 256 threads, 2x4 microtile.
// ---------------------------------------------------------------------------
__global__ __launch_bounds__(256)
void gemm_abt3_kernel(const float* __restrict__ enc, const float* __restrict__ We, const float* __restrict__ be,
                      const float* __restrict__ dh,  const float* __restrict__ Wt, const float* __restrict__ bt,
                      const float* __restrict__ lo,  const float* __restrict__ Wl, const float* __restrict__ bl)
{
    const float* A; const float* B; const float* bias; float* C;
    int z = blockIdx.z;
    if (z == 0)      { A = enc; B = We; bias = be; C = g_att1; }
    else if (z == 1) { A = dh;  B = Wt; bias = bt; C = g_att2; }
    else             { A = lo;  B = Wl; bias = bl; C = g_att3; }

    __shared__ float As[16][36];   // [k][m], padded
    __shared__ float Bs[16][68];   // [k][n], padded

    const int tid = threadIdx.x;
    const int tx  = tid & 15;       // n micro index (4 cols)
    const int ty  = tid >> 4;       // m micro index (2 rows)
    const int m0  = blockIdx.y * 32;
    const int n0  = blockIdx.x * 64;

    float acc[2][4] = {};

    const int lk = tid & 15;
    const int lr = tid >> 4;        // 0..15

    for (int k0 = 0; k0 < E_DIM; k0 += 16) {
        __syncthreads();
        #pragma unroll
        for (int i = 0; i < 2; i++)
            As[lk][lr + 16 * i] = A[(m0 + lr + 16 * i) * E_DIM + k0 + lk];
        #pragma unroll
        for (int i = 0; i < 4; i++)
            Bs[lk][lr + 16 * i] = B[(n0 + lr + 16 * i) * E_DIM + k0 + lk];
        __syncthreads();

        #pragma unroll
        for (int kk = 0; kk < 16; kk++) {
            float a0 = As[kk][ty * 2 + 0];
            float a1 = As[kk][ty * 2 + 1];
            float4 rb = *(const float4*)&Bs[kk][tx * 4];
            acc[0][0] += a0 * rb.x; acc[0][1] += a0 * rb.y;
            acc[0][2] += a0 * rb.z; acc[0][3] += a0 * rb.w;
            acc[1][0] += a1 * rb.x; acc[1][1] += a1 * rb.y;
            acc[1][2] += a1 * rb.z; acc[1][3] += a1 * rb.w;
        }
    }

    float4 bv = *(const float4*)&bias[n0 + tx * 4];
    #pragma unroll
    for (int i = 0; i < 2; i++) {
        float4 o;
        o.x = acc[i][0] + bv.x;
        o.y = acc[i][1] + bv.y;
        o.z = acc[i][2] + bv.z;
        o.w = acc[i][3] + bv.w;
        *(float4*)&C[(m0 + ty * 2 + i) * A_DIM + n0 + tx * 4] = o;
    }
}

// ---------------------------------------------------------------------------
// Kernel 2: att[n,p] = sum_a relu(att1[p,a] + att2[n,a] + att3[n,a]) * Wf[a]
// (bf is a uniform shift -> cancels in softmax -> omitted)
// Block computes a 64(n) x 64(p) tile; A staged in chunks of 64 in shared,
// layout [a][row] for conflict-free float4 reads. 256 threads, 4x4 microtile.
// ---------------------------------------------------------------------------
#define CA 64
__global__ __launch_bounds__(256)
void att_main_kernel(const float* __restrict__ Wf)
{
    __shared__ float s1 [CA][68];   // [a][p]
    __shared__ float s23[CA][68];   // [a][n]
    __shared__ float sw[A_DIM];

    const int tid = threadIdx.x;
    const int tx  = tid & 15;       // p micro (4)
    const int ty  = tid >> 4;       // n micro (4)
    const int p0  = blockIdx.x * 64;
    const int n0  = blockIdx.y * 64;

    if (tid < A_DIM) sw[tid] = Wf[tid];

    float acc[4][4] = {};           // [j:n][i:p]

    const int la = tid & 63;        // a within chunk
    const int lr = tid >> 6;        // 0..3

    for (int a0 = 0; a0 < A_DIM; a0 += CA) {
        __syncthreads();
        #pragma unroll
        for (int i = 0; i < 16; i++) {
            int r = lr + 4 * i;     // 0..63
            s1 [la][r] = g_att1[(p0 + r) * A_DIM + a0 + la];
            s23[la][r] = g_att2[(n0 + r) * A_DIM + a0 + la]
                       + g_att3[(n0 + r) * A_DIM + a0 + la];
        }
        __syncthreads();

        #pragma unroll 8
        for (int a = 0; a < CA; a++) {
            float wa = sw[a0 + a];
            float4 r1 = *(const float4*)&s1 [a][tx * 4];
            float4 r2 = *(const float4*)&s23[a][ty * 4];
            float x1[4] = {r1.x, r1.y, r1.z, r1.w};
            float x2[4] = {r2.x, r2.y, r2.z, r2.w};
            #pragma unroll
            for (int j = 0; j < 4; j++) {
                #pragma unroll
                for (int i = 0; i < 4; i++) {
                    acc[j][i] += fmaxf(x1[i] + x2[j], 0.0f) * wa;
                }
            }
        }
    }

    #pragma unroll
    for (int j = 0; j < 4; j++) {
        float4 o = make_float4(acc[j][0], acc[j][1], acc[j][2], acc[j][3]);
        *(float4*)&g_att[(n0 + ty * 4 + j) * P_PIX + p0 + tx * 4] = o;
    }
}

// ---------------------------------------------------------------------------
// Kernel 3: row softmax over P, write alpha
// ---------------------------------------------------------------------------
__global__ __launch_bounds__(256)
void softmax_kernel(float* __restrict__ alpha)
{
    const int n   = blockIdx.x;
    const int tid = threadIdx.x;        // 256
    const float* row = g_att + n * P_PIX;

    __shared__ float wred[8];
    __shared__ float bm, bs;

    float x[4];
    float m = -1e30f;
    #pragma unroll
    for (int i = 0; i < 4; i++) {
        x[i] = row[tid + 256 * i];
        m = fmaxf(m, x[i]);
    }
    #pragma unroll
    for (int o = 16; o > 0; o >>= 1) m = fmaxf(m, __shfl_xor_sync(0xffffffffu, m, o));
    if ((tid & 31) == 0) wred[tid >> 5] = m;
    __syncthreads();
    if (tid == 0) {
        float v = wred[0];
        #pragma unroll
        for (int k = 1; k < 8; k++) v = fmaxf(v, wred[k]);
        bm = v;
    }
    __syncthreads();
    m = bm;

    float s = 0.0f;
    #pragma unroll
    for (int i = 0; i < 4; i++) {
        x[i] = __expf(x[i] - m);
        s += x[i];
    }
    #pragma unroll
    for (int o = 16; o > 0; o >>= 1) s += __shfl_xor_sync(0xffffffffu, s, o);
    __syncthreads();                     // protect wred reuse
    if ((tid & 31) == 0) wred[tid >> 5] = s;
    __syncthreads();
    if (tid == 0) {
        float v = 0.0f;
        #pragma unroll
        for (int k = 0; k < 8; k++) v += wred[k];
        bs = v;
    }
    __syncthreads();
    float inv = 1.0f / bs;

    #pragma unroll
    for (int i = 0; i < 4; i++)
        alpha[n * P_PIX + tid + 256 * i] = x[i] * inv;
}

// ---------------------------------------------------------------------------
// Kernel 4: awe = alpha @ enc   (M=1024, N=512, K=1024)
// BM=32, BN=64, BK=16, 256 threads, 2x4 microtile. B is K-major-by-row (A*B).
// ---------------------------------------------------------------------------
__global__ __launch_bounds__(256)
void gemm_ab_kernel(const float* __restrict__ A,   // alpha (N, P)
                    const float* __restrict__ B,   // enc   (P, E)
                    float* __restrict__ C)         // awe   (N, E)
{
    __shared__ float As[16][36];   // [k][m]
    __shared__ float Bs[16][68];   // [k][n]

    const int tid = threadIdx.x;
    const int tx  = tid & 15;
    const int ty  = tid >> 4;
    const int m0  = blockIdx.y * 32;
    const int n0  = blockIdx.x * 64;

    float acc[2][4] = {};

    const int lk  = tid & 15;
    const int lm  = tid >> 4;      // 0..15
    const int ln  = tid & 63;
    const int lkb = tid >> 6;      // 0..3

    for (int k0 = 0; k0 < P_PIX; k0 += 16) {
        __syncthreads();
        #pragma unroll
        for (int i = 0; i < 2; i++)
            As[lk][lm + 16 * i] = A[(m0 + lm + 16 * i) * P_PIX + k0 + lk];
        #pragma unroll
        for (int i = 0; i < 4; i++)
            Bs[lkb + 4 * i][ln] = B[(k0 + lkb + 4 * i) * E_DIM + n0 + ln];
        __syncthreads();

        #pragma unroll
        for (int kk = 0; kk < 16; kk++) {
            float a0 = As[kk][ty * 2 + 0];
            float a1 = As[kk][ty * 2 + 1];
            float4 rb = *(const float4*)&Bs[kk][tx * 4];
            acc[0][0] += a0 * rb.x; acc[0][1] += a0 * rb.y;
            acc[0][2] += a0 * rb.z; acc[0][3] += a0 * rb.w;
            acc[1][0] += a1 * rb.x; acc[1][1] += a1 * rb.y;
            acc[1][2] += a1 * rb.z; acc[1][3] += a1 * rb.w;
        }
    }

    #pragma unroll
    for (int i = 0; i < 2; i++) {
        float4 o = make_float4(acc[i][0], acc[i][1], acc[i][2], acc[i][3]);
        *(float4*)&C[(m0 + ty * 2 + i) * E_DIM + n0 + tx * 4] = o;
    }
}

// ---------------------------------------------------------------------------
// Launch
// ---------------------------------------------------------------------------
extern "C" void kernel_launch(void* const* d_in, const int* in_sizes, int n_in,
                              void* d_out, int out_size)
{
    (void)in_sizes; (void)n_in; (void)out_size;
    const float* enc = (const float*)d_in[0];   // (1, P, ENC)
    const float* dh  = (const float*)d_in[1];   // (N, TAG)
    const float* lo  = (const float*)d_in[2];   // (N, LANG)
    const float* We  = (const float*)d_in[3];   // (ATT, ENC)
    const float* be  = (const float*)d_in[4];
    const float* Wt  = (const float*)d_in[5];
    const float* bt  = (const float*)d_in[6];
    const float* Wl  = (const float*)d_in[7];
    const float* bl  = (const float*)d_in[8];
    const float* Wf  = (const float*)d_in[9];   // (1, ATT)
    // d_in[10] = bf: uniform shift, cancels in softmax -> unused.

    float* awe   = (float*)d_out;                       // (N, ENC) first
    float* alpha = (float*)d_out + N_ROWS * E_DIM;      // (N, P) second

    // 1) att1/att2/att3
    dim3 g1(A_DIM / 64, N_ROWS / 32, 3);
    gemm_abt3_kernel<<<g1, 256>>>(enc, We, be, dh, Wt, bt, lo, Wl, bl);

    // 2) fused relu-dot scores
    dim3 g2(P_PIX / 64, N_ROWS / 64);
    att_main_kernel<<<g2, 256>>>(Wf);

    // 3) softmax rows -> alpha (directly into output)
    softmax_kernel<<<N_ROWS, 256>>>(alpha);

    // 4) awe = alpha @ enc
    dim3 g4(E_DIM / 64, N_ROWS / 32);
    gemm_ab_kernel<<<g4, 256>>>(alpha, enc, awe);
}